// round 12
// baseline (speedup 1.0000x reference)
#include <cuda_runtime.h>
#include <cuda_fp16.h>

#define N_NODES 100000
#define N_EDGES 3200000
#define D 128
#define SCAN_B 1024
#define N_SBLK ((N_NODES + SCAN_B - 1) / SCAN_B)   // 98
#define CHUNK 8                                     // nodes per work-steal grab
#define N_CHUNKS ((N_NODES + CHUNK - 1) / CHUNK)

// ---------------- static device scratch (no allocation allowed) ----------------
__device__ __half    g_Y[(size_t)N_NODES * D];   // F @ W^T in fp16  (25.6 MB)
__device__ unsigned  g_edge[N_EDGES];            // src<<15 | norm_q15 (12.8 MB)
__device__ int       g_rank[N_EDGES];            // within-node rank (12.8 MB)
__device__ int       g_cnt[N_NODES];             // histogram
__device__ int       g_off[N_NODES + 1];         // CSR offsets
__device__ int       g_bsum[N_SBLK];             // per-block sums
__device__ int       g_bpref[N_SBLK];            // exclusive prefix of block sums
__device__ unsigned  g_ticket;                   // work-steal cursor

// ---------------- host-side stream/event resources (created pre-main) ----------
struct HostRes {
    cudaStream_t s;
    cudaEvent_t  fork_ev, join_ev;
    void* cnt_addr = nullptr;
    void* ticket_addr = nullptr;
    HostRes() {
        cudaStreamCreateWithFlags(&s, cudaStreamNonBlocking);
        cudaEventCreateWithFlags(&fork_ev, cudaEventDisableTiming);
        cudaEventCreateWithFlags(&join_ev, cudaEventDisableTiming);
    }
};
static HostRes g_res;

// ---------------------------------------------------------------------------
// histogram of dst, capturing each edge's within-node rank
// ---------------------------------------------------------------------------
__global__ __launch_bounds__(256) void hist_kernel(const int* __restrict__ dst) {
    int i = blockIdx.x * blockDim.x + threadIdx.x;
    if (i < N_EDGES)
        g_rank[i] = atomicAdd(&g_cnt[__ldg(dst + i)], 1);
}

// ---------------------------------------------------------------------------
// scan stage 1: per-block sums of g_cnt (98 blocks x 1024)
// ---------------------------------------------------------------------------
__global__ __launch_bounds__(SCAN_B) void blocksum_kernel() {
    __shared__ int sh[SCAN_B / 32];
    int idx = blockIdx.x * SCAN_B + threadIdx.x;
    int v = (idx < N_NODES) ? g_cnt[idx] : 0;
#pragma unroll
    for (int o = 16; o > 0; o >>= 1) v += __shfl_xor_sync(0xffffffffu, v, o);
    if ((threadIdx.x & 31) == 0) sh[threadIdx.x >> 5] = v;
    __syncthreads();
    if (threadIdx.x < 32) {
        int w = (threadIdx.x < SCAN_B / 32) ? sh[threadIdx.x] : 0;
#pragma unroll
        for (int o = 16; o > 0; o >>= 1) w += __shfl_xor_sync(0xffffffffu, w, o);
        if (threadIdx.x == 0) g_bsum[blockIdx.x] = w;
    }
}

// ---------------------------------------------------------------------------
// scan stage 2: exclusive scan of 98 block sums (one tiny block)
// ---------------------------------------------------------------------------
__global__ __launch_bounds__(128) void scan_bsum_kernel() {
    __shared__ int sh[128];
    int tid = threadIdx.x;
    int v = (tid < N_SBLK) ? g_bsum[tid] : 0;
    sh[tid] = v;
    __syncthreads();
    for (int o = 1; o < 128; o <<= 1) {
        int t = (tid >= o) ? sh[tid - o] : 0;
        __syncthreads();
        sh[tid] += t;
        __syncthreads();
    }
    if (tid < N_SBLK) g_bpref[tid] = sh[tid] - v;   // exclusive
}

// ---------------------------------------------------------------------------
// scan stage 3: per-block scan + block prefix -> g_off
// ---------------------------------------------------------------------------
__global__ __launch_bounds__(SCAN_B) void offsets_kernel() {
    __shared__ int sh[SCAN_B];
    int tid = threadIdx.x;
    int idx = blockIdx.x * SCAN_B + tid;
    int v = (idx < N_NODES) ? g_cnt[idx] : 0;
    sh[tid] = v;
    __syncthreads();
    for (int o = 1; o < SCAN_B; o <<= 1) {
        int t = (tid >= o) ? sh[tid - o] : 0;
        __syncthreads();
        sh[tid] += t;
        __syncthreads();
    }
    if (idx < N_NODES)
        g_off[idx] = g_bpref[blockIdx.x] + sh[tid] - v;
    if (idx == 0) g_off[N_NODES] = N_EDGES;
}

// ---------------------------------------------------------------------------
// fill CSR edge list WITHOUT atomics: pos = off[dst] + rank
// packed edge word: (src << 15) | floor(norm * 32768)   [norm in [0,1)]
// ---------------------------------------------------------------------------
__global__ __launch_bounds__(256) void fill_kernel(const int* __restrict__ src,
                                                   const int* __restrict__ dst,
                                                   const float* __restrict__ norm) {
    int i = blockIdx.x * blockDim.x + threadIdx.x;
    if (i < N_EDGES) {
        int d   = __ldg(dst + i);
        int pos = __ldg(&g_off[d]) + __ldg(&g_rank[i]);
        unsigned q = (unsigned)(__ldg(norm + i) * 32768.0f);
        if (q > 32767u) q = 32767u;
        g_edge[pos] = ((unsigned)__ldg(src + i) << 15) | q;
    }
}

// ---------------------------------------------------------------------------
// Y = F @ W^T   (fp32 compute, fp16 store); 128x128 tile, BK=16, 8x8/thread
// ---------------------------------------------------------------------------
__global__ __launch_bounds__(256) void gemm_kernel(const float* __restrict__ F,
                                                   const float* __restrict__ W) {
    const int BM = 128, BK = 16, TM = 8, TN = 8;
    __shared__ float Fs[BK][BM];
    __shared__ float Ws[BK][BM];

    const int tid = threadIdx.x;
    const int tn = (tid % 16) * TN;
    const int tm = (tid / 16) * TM;
    const int m0 = blockIdx.x * BM;

    float acc[TM][TN];
#pragma unroll
    for (int i = 0; i < TM; i++)
#pragma unroll
        for (int j = 0; j < TN; j++) acc[i][j] = 0.0f;

    for (int kt = 0; kt < D; kt += BK) {
#pragma unroll
        for (int l = 0; l < 2; l++) {
            int idx = tid * 2 + l;
            int m   = idx >> 2;
            int kq  = idx & 3;
            float4 v = make_float4(0.f, 0.f, 0.f, 0.f);
            if (m0 + m < N_NODES)
                v = *(const float4*)(F + (size_t)(m0 + m) * D + kt + kq * 4);
            Fs[kq * 4 + 0][m] = v.x;
            Fs[kq * 4 + 1][m] = v.y;
            Fs[kq * 4 + 2][m] = v.z;
            Fs[kq * 4 + 3][m] = v.w;
        }
#pragma unroll
        for (int l = 0; l < 2; l++) {
            int idx = tid * 2 + l;
            int c   = idx >> 2;
            int kq  = idx & 3;
            float4 v = *(const float4*)(W + (size_t)c * D + kt + kq * 4);
            Ws[kq * 4 + 0][c] = v.x;
            Ws[kq * 4 + 1][c] = v.y;
            Ws[kq * 4 + 2][c] = v.z;
            Ws[kq * 4 + 3][c] = v.w;
        }
        __syncthreads();

#pragma unroll
        for (int k = 0; k < BK; k++) {
            float rm[TM], rn[TN];
            float4 a0 = *(const float4*)&Fs[k][tm];
            float4 a1 = *(const float4*)&Fs[k][tm + 4];
            float4 b0 = *(const float4*)&Ws[k][tn];
            float4 b1 = *(const float4*)&Ws[k][tn + 4];
            rm[0] = a0.x; rm[1] = a0.y; rm[2] = a0.z; rm[3] = a0.w;
            rm[4] = a1.x; rm[5] = a1.y; rm[6] = a1.z; rm[7] = a1.w;
            rn[0] = b0.x; rn[1] = b0.y; rn[2] = b0.z; rn[3] = b0.w;
            rn[4] = b1.x; rn[5] = b1.y; rn[6] = b1.z; rn[7] = b1.w;
#pragma unroll
            for (int i = 0; i < TM; i++)
#pragma unroll
                for (int j = 0; j < TN; j++)
                    acc[i][j] = fmaf(rm[i], rn[j], acc[i][j]);
        }
        __syncthreads();
    }

#pragma unroll
    for (int i = 0; i < TM; i++) {
        int m = m0 + tm + i;
        if (m < N_NODES) {
            __half2 h[4];
#pragma unroll
            for (int j = 0; j < 4; j++)
                h[j] = __floats2half2_rn(acc[i][2 * j], acc[i][2 * j + 1]);
            *(uint4*)(g_Y + (size_t)m * D + tn) = *(uint4*)h;
        }
    }
}

// ---------------------------------------------------------------------------
// per-node reduction with warp-level work stealing: each warp grabs CHUNK
// nodes at a time from a global ticket. Per-node body identical to the
// proven R8 loop (half-warp covers a 256B Y row; 4 edge words + 4 gathers
// batched; .cs streaming hints protect Y's L2 residency).
// ---------------------------------------------------------------------------
__device__ __forceinline__ void fma8(float acc[8], uint4 u, float n) {
    float2 f0 = __half22float2(*(__half2*)&u.x);
    float2 f1 = __half22float2(*(__half2*)&u.y);
    float2 f2 = __half22float2(*(__half2*)&u.z);
    float2 f3 = __half22float2(*(__half2*)&u.w);
    acc[0] = fmaf(n, f0.x, acc[0]); acc[1] = fmaf(n, f0.y, acc[1]);
    acc[2] = fmaf(n, f1.x, acc[2]); acc[3] = fmaf(n, f1.y, acc[3]);
    acc[4] = fmaf(n, f2.x, acc[4]); acc[5] = fmaf(n, f2.y, acc[5]);
    acc[6] = fmaf(n, f3.x, acc[6]); acc[7] = fmaf(n, f3.y, acc[7]);
}

__global__ __launch_bounds__(256) void reduce_kernel(float* __restrict__ out,
                                                     const float* __restrict__ bias) {
    int lane = threadIdx.x & 31;
    int half = lane >> 4;        // which of the 2 interleaved edge streams
    int hl   = lane & 15;        // 16 lanes x 8 halfs = 128 cols

    const __half* Ycol = g_Y + hl * 8;
    const float4* b4 = (const float4*)bias;
    float4 b0 = b4[hl * 2], b1 = b4[hl * 2 + 1];

    for (;;) {
        unsigned t;
        if (lane == 0) t = atomicAdd(&g_ticket, 1u);
        t = __shfl_sync(0xffffffffu, t, 0);
        int n0 = (int)t * CHUNK;
        if (n0 >= N_NODES) break;
        int n1 = n0 + CHUNK < N_NODES ? n0 + CHUNK : N_NODES;

        for (int node = n0; node < n1; node++) {
            int beg = __ldg(&g_off[node]);
            int end = __ldg(&g_off[node + 1]);

            float acc[8] = {0.f, 0.f, 0.f, 0.f, 0.f, 0.f, 0.f, 0.f};

            int e = beg + half;
            for (; e + 6 < end; e += 8) {
                unsigned w0 = __ldcs(&g_edge[e]);
                unsigned w1 = __ldcs(&g_edge[e + 2]);
                unsigned w2 = __ldcs(&g_edge[e + 4]);
                unsigned w3 = __ldcs(&g_edge[e + 6]);
                uint4 u0 = *(const uint4*)(Ycol + (size_t)(w0 >> 15) * D);
                uint4 u1 = *(const uint4*)(Ycol + (size_t)(w1 >> 15) * D);
                uint4 u2 = *(const uint4*)(Ycol + (size_t)(w2 >> 15) * D);
                uint4 u3 = *(const uint4*)(Ycol + (size_t)(w3 >> 15) * D);
                fma8(acc, u0, (float)(w0 & 0x7FFFu) * (1.0f / 32768.0f));
                fma8(acc, u1, (float)(w1 & 0x7FFFu) * (1.0f / 32768.0f));
                fma8(acc, u2, (float)(w2 & 0x7FFFu) * (1.0f / 32768.0f));
                fma8(acc, u3, (float)(w3 & 0x7FFFu) * (1.0f / 32768.0f));
            }
            for (; e < end; e += 2) {
                unsigned w = __ldcs(&g_edge[e]);
                uint4 u = *(const uint4*)(Ycol + (size_t)(w >> 15) * D);
                fma8(acc, u, (float)(w & 0x7FFFu) * (1.0f / 32768.0f));
            }

#pragma unroll
            for (int j = 0; j < 8; j++)
                acc[j] += __shfl_xor_sync(0xffffffffu, acc[j], 16);

            if (half == 0) {
                float4* o = (float4*)(out + (size_t)node * D + hl * 8);
                __stcs(o,     make_float4(acc[0] + b0.x, acc[1] + b0.y,
                                          acc[2] + b0.z, acc[3] + b0.w));
                __stcs(o + 1, make_float4(acc[4] + b1.x, acc[5] + b1.y,
                                          acc[6] + b1.z, acc[7] + b1.w));
            }
        }
    }
}

// ---------------------------------------------------------------------------
extern "C" void kernel_launch(void* const* d_in, const int* in_sizes, int n_in,
                              void* d_out, int out_size) {
    const float* features = (const float*)d_in[0];
    const float* norm     = (const float*)d_in[1];
    const int*   src      = (const int*)d_in[2];
    const int*   dst      = (const int*)d_in[3];
    const float* weight   = (const float*)d_in[4];
    const float* bias     = (const float*)d_in[5];
    float*       out      = (float*)d_out;

    if (!g_res.cnt_addr)    cudaGetSymbolAddress(&g_res.cnt_addr, g_cnt);
    if (!g_res.ticket_addr) cudaGetSymbolAddress(&g_res.ticket_addr, g_ticket);

    // Fork: GEMM on side stream, concurrent with the CSR sort pipeline.
    cudaEventRecord(g_res.fork_ev, 0);
    cudaStreamWaitEvent(g_res.s, g_res.fork_ev, 0);
    gemm_kernel<<<(N_NODES + 127) / 128, 256, 0, g_res.s>>>(features, weight);
    cudaEventRecord(g_res.join_ev, g_res.s);

    // Main stream: counting sort by dst (rank captured in hist; fill atomic-free)
    cudaMemsetAsync(g_res.cnt_addr, 0, N_NODES * sizeof(int), 0);
    cudaMemsetAsync(g_res.ticket_addr, 0, sizeof(unsigned), 0);
    hist_kernel<<<(N_EDGES + 255) / 256, 256>>>(dst);
    blocksum_kernel<<<N_SBLK, SCAN_B>>>();
    scan_bsum_kernel<<<1, 128>>>();
    offsets_kernel<<<N_SBLK, SCAN_B>>>();
    fill_kernel<<<(N_EDGES + 255) / 256, 256>>>(src, dst, norm);

    // Join, then work-stealing reduce (8 warps/block, 1184 blocks ≈ 8/SM)
    cudaStreamWaitEvent(0, g_res.join_ev, 0);
    reduce_kernel<<<1184, 256>>>(out, bias);
}

// round 13
// speedup vs baseline: 1.1016x; 1.1016x over previous
#include <cuda_runtime.h>
#include <cuda_fp16.h>

#define N_NODES 100000
#define N_EDGES 3200000
#define D 128
#define SCAN_B 1024
#define N_SBLK ((N_NODES + SCAN_B - 1) / SCAN_B)   // 98

// ---------------- static device scratch (no allocation allowed) ----------------
__device__ __half    g_Y[(size_t)N_NODES * D];   // F @ W^T in fp16  (25.6 MB)
__device__ unsigned  g_edge[N_EDGES];            // src<<15 | norm_q15 (12.8 MB)
__device__ int       g_rank[N_EDGES];            // within-node rank (12.8 MB)
__device__ int       g_cnt[N_NODES];             // histogram
__device__ int       g_off[N_NODES + 1];         // CSR offsets
__device__ int       g_bsum[N_SBLK];             // per-block sums
__device__ int       g_bpref[N_SBLK];            // exclusive prefix of block sums

// ---------------- host-side stream/event resources (created pre-main) ----------
struct HostRes {
    cudaStream_t s;
    cudaEvent_t  fork_ev, join_ev;
    void* cnt_addr = nullptr;
    HostRes() {
        cudaStreamCreateWithFlags(&s, cudaStreamNonBlocking);
        cudaEventCreateWithFlags(&fork_ev, cudaEventDisableTiming);
        cudaEventCreateWithFlags(&join_ev, cudaEventDisableTiming);
    }
};
static HostRes g_res;

// ---------------------------------------------------------------------------
// histogram of dst, capturing each edge's within-node rank
// ---------------------------------------------------------------------------
__global__ __launch_bounds__(256) void hist_kernel(const int* __restrict__ dst) {
    int i = blockIdx.x * blockDim.x + threadIdx.x;
    if (i < N_EDGES)
        g_rank[i] = atomicAdd(&g_cnt[__ldg(dst + i)], 1);
}

// ---------------------------------------------------------------------------
// scan stage 1: per-block sums of g_cnt (98 blocks x 1024)
// ---------------------------------------------------------------------------
__global__ __launch_bounds__(SCAN_B) void blocksum_kernel() {
    __shared__ int sh[SCAN_B / 32];
    int idx = blockIdx.x * SCAN_B + threadIdx.x;
    int v = (idx < N_NODES) ? g_cnt[idx] : 0;
#pragma unroll
    for (int o = 16; o > 0; o >>= 1) v += __shfl_xor_sync(0xffffffffu, v, o);
    if ((threadIdx.x & 31) == 0) sh[threadIdx.x >> 5] = v;
    __syncthreads();
    if (threadIdx.x < 32) {
        int w = (threadIdx.x < SCAN_B / 32) ? sh[threadIdx.x] : 0;
#pragma unroll
        for (int o = 16; o > 0; o >>= 1) w += __shfl_xor_sync(0xffffffffu, w, o);
        if (threadIdx.x == 0) g_bsum[blockIdx.x] = w;
    }
}

// ---------------------------------------------------------------------------
// scan stage 2: exclusive scan of 98 block sums (one tiny block)
// ---------------------------------------------------------------------------
__global__ __launch_bounds__(128) void scan_bsum_kernel() {
    __shared__ int sh[128];
    int tid = threadIdx.x;
    int v = (tid < N_SBLK) ? g_bsum[tid] : 0;
    sh[tid] = v;
    __syncthreads();
    for (int o = 1; o < 128; o <<= 1) {
        int t = (tid >= o) ? sh[tid - o] : 0;
        __syncthreads();
        sh[tid] += t;
        __syncthreads();
    }
    if (tid < N_SBLK) g_bpref[tid] = sh[tid] - v;   // exclusive
}

// ---------------------------------------------------------------------------
// scan stage 3: per-block scan + block prefix -> g_off
// ---------------------------------------------------------------------------
__global__ __launch_bounds__(SCAN_B) void offsets_kernel() {
    __shared__ int sh[SCAN_B];
    int tid = threadIdx.x;
    int idx = blockIdx.x * SCAN_B + tid;
    int v = (idx < N_NODES) ? g_cnt[idx] : 0;
    sh[tid] = v;
    __syncthreads();
    for (int o = 1; o < SCAN_B; o <<= 1) {
        int t = (tid >= o) ? sh[tid - o] : 0;
        __syncthreads();
        sh[tid] += t;
        __syncthreads();
    }
    if (idx < N_NODES)
        g_off[idx] = g_bpref[blockIdx.x] + sh[tid] - v;
    if (idx == 0) g_off[N_NODES] = N_EDGES;
}

// ---------------------------------------------------------------------------
// fill CSR edge list WITHOUT atomics, 4 edges per thread (int4 loads, 4x MLP)
// pos = off[dst] + rank; packed word: (src << 15) | floor(norm * 32768)
// ---------------------------------------------------------------------------
__global__ __launch_bounds__(256) void fill_kernel(const int* __restrict__ src,
                                                   const int* __restrict__ dst,
                                                   const float* __restrict__ norm) {
    int i = (blockIdx.x * blockDim.x + threadIdx.x) * 4;   // N_EDGES % 4 == 0
    if (i < N_EDGES) {
        int4   d4 = *(const int4*)(dst + i);
        int4   s4 = *(const int4*)(src + i);
        float4 n4 = *(const float4*)(norm + i);
        int4   r4 = *(const int4*)(g_rank + i);

        // 4 independent off[d] L2 reads in flight
        int o0 = __ldg(&g_off[d4.x]);
        int o1 = __ldg(&g_off[d4.y]);
        int o2 = __ldg(&g_off[d4.z]);
        int o3 = __ldg(&g_off[d4.w]);

        unsigned q0 = (unsigned)(n4.x * 32768.0f); if (q0 > 32767u) q0 = 32767u;
        unsigned q1 = (unsigned)(n4.y * 32768.0f); if (q1 > 32767u) q1 = 32767u;
        unsigned q2 = (unsigned)(n4.z * 32768.0f); if (q2 > 32767u) q2 = 32767u;
        unsigned q3 = (unsigned)(n4.w * 32768.0f); if (q3 > 32767u) q3 = 32767u;

        g_edge[o0 + r4.x] = ((unsigned)s4.x << 15) | q0;
        g_edge[o1 + r4.y] = ((unsigned)s4.y << 15) | q1;
        g_edge[o2 + r4.z] = ((unsigned)s4.z << 15) | q2;
        g_edge[o3 + r4.w] = ((unsigned)s4.w << 15) | q3;
    }
}

// ---------------------------------------------------------------------------
// Y = F @ W^T   (fp32 compute, fp16 store); 128x128 tile, BK=16, 8x8/thread
// ---------------------------------------------------------------------------
__global__ __launch_bounds__(256) void gemm_kernel(const float* __restrict__ F,
                                                   const float* __restrict__ W) {
    const int BM = 128, BK = 16, TM = 8, TN = 8;
    __shared__ float Fs[BK][BM];
    __shared__ float Ws[BK][BM];

    const int tid = threadIdx.x;
    const int tn = (tid % 16) * TN;
    const int tm = (tid / 16) * TM;
    const int m0 = blockIdx.x * BM;

    float acc[TM][TN];
#pragma unroll
    for (int i = 0; i < TM; i++)
#pragma unroll
        for (int j = 0; j < TN; j++) acc[i][j] = 0.0f;

    for (int kt = 0; kt < D; kt += BK) {
#pragma unroll
        for (int l = 0; l < 2; l++) {
            int idx = tid * 2 + l;
            int m   = idx >> 2;
            int kq  = idx & 3;
            float4 v = make_float4(0.f, 0.f, 0.f, 0.f);
            if (m0 + m < N_NODES)
                v = *(const float4*)(F + (size_t)(m0 + m) * D + kt + kq * 4);
            Fs[kq * 4 + 0][m] = v.x;
            Fs[kq * 4 + 1][m] = v.y;
            Fs[kq * 4 + 2][m] = v.z;
            Fs[kq * 4 + 3][m] = v.w;
        }
#pragma unroll
        for (int l = 0; l < 2; l++) {
            int idx = tid * 2 + l;
            int c   = idx >> 2;
            int kq  = idx & 3;
            float4 v = *(const float4*)(W + (size_t)c * D + kt + kq * 4);
            Ws[kq * 4 + 0][c] = v.x;
            Ws[kq * 4 + 1][c] = v.y;
            Ws[kq * 4 + 2][c] = v.z;
            Ws[kq * 4 + 3][c] = v.w;
        }
        __syncthreads();

#pragma unroll
        for (int k = 0; k < BK; k++) {
            float rm[TM], rn[TN];
            float4 a0 = *(const float4*)&Fs[k][tm];
            float4 a1 = *(const float4*)&Fs[k][tm + 4];
            float4 b0 = *(const float4*)&Ws[k][tn];
            float4 b1 = *(const float4*)&Ws[k][tn + 4];
            rm[0] = a0.x; rm[1] = a0.y; rm[2] = a0.z; rm[3] = a0.w;
            rm[4] = a1.x; rm[5] = a1.y; rm[6] = a1.z; rm[7] = a1.w;
            rn[0] = b0.x; rn[1] = b0.y; rn[2] = b0.z; rn[3] = b0.w;
            rn[4] = b1.x; rn[5] = b1.y; rn[6] = b1.z; rn[7] = b1.w;
#pragma unroll
            for (int i = 0; i < TM; i++)
#pragma unroll
                for (int j = 0; j < TN; j++)
                    acc[i][j] = fmaf(rm[i], rn[j], acc[i][j]);
        }
        __syncthreads();
    }

#pragma unroll
    for (int i = 0; i < TM; i++) {
        int m = m0 + tm + i;
        if (m < N_NODES) {
            __half2 h[4];
#pragma unroll
            for (int j = 0; j < 4; j++)
                h[j] = __floats2half2_rn(acc[i][2 * j], acc[i][2 * j + 1]);
            *(uint4*)(g_Y + (size_t)m * D + tn) = *(uint4*)h;
        }
    }
}

// ---------------------------------------------------------------------------
// per-node reduction (R8/R11 proven form): one warp/node, half-warp covers a
// 256B Y row, lane owns 8 halfs (LDG.128); counted loop, 4 edge words + 4
// gathers batched per iteration; .cs on edges/out to keep Y in L2.
// ---------------------------------------------------------------------------
__device__ __forceinline__ void fma8(float acc[8], uint4 u, float n) {
    float2 f0 = __half22float2(*(__half2*)&u.x);
    float2 f1 = __half22float2(*(__half2*)&u.y);
    float2 f2 = __half22float2(*(__half2*)&u.z);
    float2 f3 = __half22float2(*(__half2*)&u.w);
    acc[0] = fmaf(n, f0.x, acc[0]); acc[1] = fmaf(n, f0.y, acc[1]);
    acc[2] = fmaf(n, f1.x, acc[2]); acc[3] = fmaf(n, f1.y, acc[3]);
    acc[4] = fmaf(n, f2.x, acc[4]); acc[5] = fmaf(n, f2.y, acc[5]);
    acc[6] = fmaf(n, f3.x, acc[6]); acc[7] = fmaf(n, f3.y, acc[7]);
}

__device__ __forceinline__ void edge_fma(float acc[8], const __half* Ycol, unsigned w) {
    unsigned s = w >> 15;
    float   n = (float)(w & 0x7FFFu) * (1.0f / 32768.0f);
    uint4   u = *(const uint4*)(Ycol + (size_t)s * D);
    fma8(acc, u, n);
}

__global__ __launch_bounds__(256) void reduce_kernel(float* __restrict__ out,
                                                     const float* __restrict__ bias) {
    int warp = (blockIdx.x * blockDim.x + threadIdx.x) >> 5;
    int lane = threadIdx.x & 31;
    if (warp >= N_NODES) return;

    int beg = __ldg(&g_off[warp]);
    int end = __ldg(&g_off[warp + 1]);

    int half = lane >> 4;
    int hl   = lane & 15;

    float acc[8] = {0.f, 0.f, 0.f, 0.f, 0.f, 0.f, 0.f, 0.f};
    const __half* Ycol = g_Y + hl * 8;

    int e = beg + half;
    for (; e + 6 < end; e += 8) {
        unsigned w0 = __ldcs(&g_edge[e]);
        unsigned w1 = __ldcs(&g_edge[e + 2]);
        unsigned w2 = __ldcs(&g_edge[e + 4]);
        unsigned w3 = __ldcs(&g_edge[e + 6]);
        unsigned s0 = w0 >> 15, s1 = w1 >> 15, s2 = w2 >> 15, s3 = w3 >> 15;
        uint4 u0 = *(const uint4*)(Ycol + (size_t)s0 * D);
        uint4 u1 = *(const uint4*)(Ycol + (size_t)s1 * D);
        uint4 u2 = *(const uint4*)(Ycol + (size_t)s2 * D);
        uint4 u3 = *(const uint4*)(Ycol + (size_t)s3 * D);
        fma8(acc, u0, (float)(w0 & 0x7FFFu) * (1.0f / 32768.0f));
        fma8(acc, u1, (float)(w1 & 0x7FFFu) * (1.0f / 32768.0f));
        fma8(acc, u2, (float)(w2 & 0x7FFFu) * (1.0f / 32768.0f));
        fma8(acc, u3, (float)(w3 & 0x7FFFu) * (1.0f / 32768.0f));
    }
    for (; e < end; e += 2)
        edge_fma(acc, Ycol, __ldcs(&g_edge[e]));

#pragma unroll
    for (int j = 0; j < 8; j++)
        acc[j] += __shfl_xor_sync(0xffffffffu, acc[j], 16);

    if (half == 0) {
        const float4* b4 = (const float4*)bias;
        float4 b0 = b4[hl * 2], b1 = b4[hl * 2 + 1];
        float4* o = (float4*)(out + (size_t)warp * D + hl * 8);
        __stcs(o,     make_float4(acc[0] + b0.x, acc[1] + b0.y,
                                  acc[2] + b0.z, acc[3] + b0.w));
        __stcs(o + 1, make_float4(acc[4] + b1.x, acc[5] + b1.y,
                                  acc[6] + b1.z, acc[7] + b1.w));
    }
}

// ---------------------------------------------------------------------------
extern "C" void kernel_launch(void* const* d_in, const int* in_sizes, int n_in,
                              void* d_out, int out_size) {
    const float* features = (const float*)d_in[0];
    const float* norm     = (const float*)d_in[1];
    const int*   src      = (const int*)d_in[2];
    const int*   dst      = (const int*)d_in[3];
    const float* weight   = (const float*)d_in[4];
    const float* bias     = (const float*)d_in[5];
    float*       out      = (float*)d_out;

    if (!g_res.cnt_addr) cudaGetSymbolAddress(&g_res.cnt_addr, g_cnt);

    // Fork: GEMM on side stream, concurrent with the CSR sort pipeline.
    cudaEventRecord(g_res.fork_ev, 0);
    cudaStreamWaitEvent(g_res.s, g_res.fork_ev, 0);
    gemm_kernel<<<(N_NODES + 127) / 128, 256, 0, g_res.s>>>(features, weight);
    cudaEventRecord(g_res.join_ev, g_res.s);

    // Main stream: counting sort by dst (rank captured in hist; fill atomic-free)
    cudaMemsetAsync(g_res.cnt_addr, 0, N_NODES * sizeof(int), 0);
    hist_kernel<<<(N_EDGES + 255) / 256, 256>>>(dst);
    blocksum_kernel<<<N_SBLK, SCAN_B>>>();
    scan_bsum_kernel<<<1, 128>>>();
    offsets_kernel<<<N_SBLK, SCAN_B>>>();
    fill_kernel<<<(N_EDGES / 4 + 255) / 256, 256>>>(src, dst, norm);

    // Join, then reduce (one warp per node)
    cudaStreamWaitEvent(0, g_res.join_ev, 0);
    long long total_threads = (long long)N_NODES * 32;
    reduce_kernel<<<(int)((total_threads + 255) / 256), 256>>>(out, bias);
}